// round 14
// baseline (speedup 1.0000x reference)
#include <cuda_runtime.h>
#include <cuda_fp16.h>
#include <math.h>
#include <stdint.h>

// MoE Router: 1-term fp16 mma.sync GEMM (BM=64, 2 CTAs/SM, 3-stage pipeline)
// + candidate-only exact fp32 refinement of marginal tokens.
// T=16384, D=4096, E=64, top-2.
// Output (float32): logits [T,E] | weights [T,2] | indices [T,2] | mask [E,2,T]

#define Dk 4096
#define Ek 64
#define TOPK 2
#define BM 64
#define KC 64
#define NCHUNK (Dk / KC)
#define NTHR 256
#define THETA    2.5e-3f
#define CAND_WIN 5.0e-3f

__device__ __half g_w1[Ek * Dk];    // fp16 gate weights, [E][Dk] k-major
__device__ int    g_flagcnt;
__device__ int    g_flags[16384];

// ---------------- smem layout: 3 stages of (X 8KB | W 8KB) ----------------
#define SM_BIAS 64
#define STG(s)  (1024 + (s) * 16384)
#define XS(s)   STG(s)
#define WS(s)   (STG(s) + 8192)
#define SM_LG   1024
#define SMEM_TOTAL (1024 + 3 * 16384)

// ---------------- helpers ----------------
__device__ __forceinline__ uint32_t smem_u32(const void* p) {
    uint32_t a;
    asm("{ .reg .u64 t; cvta.to.shared.u64 t, %1; cvt.u32.u64 %0, t; }" : "=r"(a) : "l"(p));
    return a;
}
__device__ __forceinline__ uint32_t pack2h(float hi, float lo) {
    uint32_t r;
    asm("cvt.rn.f16x2.f32 %0, %1, %2;" : "=r"(r) : "f"(hi), "f"(lo));
    return r;
}
__device__ __forceinline__ uint2 cvt4h(float4 v) {
    return make_uint2(pack2h(v.y, v.x), pack2h(v.w, v.z));
}
__device__ __forceinline__ void ldm_x4(uint32_t* r, uint32_t addr) {
    asm volatile("ldmatrix.sync.aligned.m8n8.x4.shared.b16 {%0,%1,%2,%3}, [%4];"
        : "=r"(r[0]), "=r"(r[1]), "=r"(r[2]), "=r"(r[3]) : "r"(addr));
}
__device__ __forceinline__ void mma_f16(float* c, const uint32_t* a, uint32_t b0, uint32_t b1) {
    asm volatile("mma.sync.aligned.m16n8k16.row.col.f32.f16.f16.f32 "
        "{%0,%1,%2,%3}, {%4,%5,%6,%7}, {%8,%9}, {%0,%1,%2,%3};"
        : "+f"(c[0]), "+f"(c[1]), "+f"(c[2]), "+f"(c[3])
        : "r"(a[0]), "r"(a[1]), "r"(a[2]), "r"(a[3]), "r"(b0), "r"(b1));
}

// ---------------- aux: convert w to fp16 + reset flag counter ----------------
__global__ void w_prep_kernel(const float4* __restrict__ gw4) {
    int i = blockIdx.x * blockDim.x + threadIdx.x;
    if (i == 0) g_flagcnt = 0;
    ((uint2*)g_w1)[i] = cvt4h(gw4[i]);
}

// ---------------- pass 1 ----------------
__global__ __launch_bounds__(NTHR, 2)
void moe_router_mma(const float* __restrict__ x,
                    const float* __restrict__ gb,
                    float* __restrict__ out, int T)
{
    extern __shared__ char smem[];
    const uint32_t sb = smem_u32(smem);
    const int tid = threadIdx.x;
    const int lid = tid & 31;
    const int wid = tid >> 5;
    const int t0 = blockIdx.x * BM;

    const size_t offW = (size_t)T * Ek;
    const size_t offI = offW + (size_t)T * TOPK;
    const size_t offM = offI + (size_t)T * TOPK;

    if (tid < 16) ((float4*)(smem + SM_BIAS))[tid] = ((const float4*)gb)[tid];

    // zero this CTA's slice of expert_mask: 128 (e,k) rows, cols [t0, t0+64)
    {
        float4 z4 = make_float4(0.f, 0.f, 0.f, 0.f);
        float* mbase = out + offM + t0;
#pragma unroll
        for (int i = tid; i < 128 * 16; i += NTHR) {
            int row = i >> 4, col = i & 15;
            ((float4*)(mbase + (size_t)row * T))[col] = z4;
        }
    }

    // ---- loader geometry ----
    // x: 64 rows x 64 fp32; 4 threads/row, 4 float4 each (segs xj+4s)
    const int xr = tid >> 2;     // row 0..63
    const int xj = tid & 3;
    uint32_t x_sts[4];
#pragma unroll
    for (int s = 0; s < 4; ++s) {
        int seg = xj + 4 * s;
        x_sts[s] = (uint32_t)(xr * 128 + ((seg * 8) ^ ((xr & 7) << 4)));
    }
    // w: 64 rows x 128B; 512 uint4 -> 2 per thread
    int wrow[2], wseg[2];
    uint32_t w_sts[2];
#pragma unroll
    for (int it = 0; it < 2; ++it) {
        int idx = it * NTHR + tid;
        wrow[it] = idx >> 3; wseg[it] = idx & 7;
        w_sts[it] = (uint32_t)(wrow[it] * 128 + ((wseg[it] * 16) ^ ((wrow[it] & 7) << 4)));
    }

    // ---- mma geometry: 8 warps, warp tile 32(m) x 16(n) ----
    const int wm = wid & 1;
    const int wn = wid >> 1;
    const int lrow = lid & 15;
    const int lhi = (lid >> 4) << 4;
    const int rsw = (lrow & 7) << 4;
    int arow[2];
#pragma unroll
    for (int mi = 0; mi < 2; ++mi) arow[mi] = (32 * wm + 16 * mi + lrow) * 128;
    const int brow = (16 * wn + lrow) * 128;

    float acc[2][2][4];
#pragma unroll
    for (int mi = 0; mi < 2; ++mi)
#pragma unroll
        for (int nj = 0; nj < 2; ++nj)
#pragma unroll
            for (int q = 0; q < 4; ++q) acc[mi][nj][q] = 0.f;

    // ---- prologue: chunk 0 -> stage 0; chunk 1 -> regs ----
    {
        const float* xp = x + (size_t)(t0 + xr) * Dk;
#pragma unroll
        for (int s = 0; s < 4; ++s)
            *(uint2*)(smem + XS(0) + x_sts[s]) = cvt4h(*(const float4*)(xp + 4 * (xj + 4 * s)));
#pragma unroll
        for (int it = 0; it < 2; ++it) {
            const size_t eoff = (size_t)wrow[it] * Dk + wseg[it] * 8;
            *(uint4*)(smem + WS(0) + w_sts[it]) = *(const uint4*)((const char*)g_w1 + eoff * 2);
        }
    }
    float4 xv[4];
    uint4 w1v[2];
    {
        const float* xp = x + (size_t)(t0 + xr) * Dk + KC;
#pragma unroll
        for (int s = 0; s < 4; ++s)
            xv[s] = *(const float4*)(xp + 4 * (xj + 4 * s));
#pragma unroll
        for (int it = 0; it < 2; ++it) {
            const size_t eoff = (size_t)wrow[it] * Dk + KC + wseg[it] * 8;
            w1v[it] = *(const uint4*)((const char*)g_w1 + eoff * 2);
        }
    }
    __syncthreads();

    // ---- main loop: STS(c+1), LDG(c+2), compute(c) ----
    int s_cur = 0, s_nxt = 1;
    for (int c = 0; c < NCHUNK; ++c) {
        if (c + 1 < NCHUNK) {
#pragma unroll
            for (int s = 0; s < 4; ++s)
                *(uint2*)(smem + XS(s_nxt) + x_sts[s]) = cvt4h(xv[s]);
#pragma unroll
            for (int it = 0; it < 2; ++it)
                *(uint4*)(smem + WS(s_nxt) + w_sts[it]) = w1v[it];
        }
        if (c + 2 < NCHUNK) {
            const int d2 = (c + 2) * KC;
            const float* xp = x + (size_t)(t0 + xr) * Dk + d2;
#pragma unroll
            for (int s = 0; s < 4; ++s)
                xv[s] = *(const float4*)(xp + 4 * (xj + 4 * s));
#pragma unroll
            for (int it = 0; it < 2; ++it) {
                const size_t eoff = (size_t)wrow[it] * Dk + d2 + wseg[it] * 8;
                w1v[it] = *(const uint4*)((const char*)g_w1 + eoff * 2);
            }
        }

        // compute chunk c from stage s_cur
        {
            const uint32_t x1_b = sb + XS(s_cur), w1_b = sb + WS(s_cur);
#pragma unroll
            for (int ks = 0; ks < 4; ++ks) {
                const uint32_t kb = (uint32_t)((ks * 32 + lhi) ^ rsw);
                uint32_t a1[2][4], b1[4];
#pragma unroll
                for (int mi = 0; mi < 2; ++mi) ldm_x4(a1[mi], x1_b + arow[mi] + kb);
                ldm_x4(b1, w1_b + brow + kb);
#pragma unroll
                for (int mi = 0; mi < 2; ++mi)
#pragma unroll
                    for (int nj = 0; nj < 2; ++nj)
                        mma_f16(acc[mi][nj], a1[mi], b1[nj], b1[nj + 2]);
            }
        }
        __syncthreads();
        s_cur = (s_cur == 2) ? 0 : s_cur + 1;
        s_nxt = (s_nxt == 2) ? 0 : s_nxt + 1;
    }

    // ---- epilogue: acc -> smem logits (64 x 64) ----
    float* lg = (float*)(smem + SM_LG);
    {
        const int crow = 32 * wm + (lid >> 2);
        const int ccol = 16 * wn + (lid & 3) * 2;
#pragma unroll
        for (int mi = 0; mi < 2; ++mi)
#pragma unroll
            for (int nj = 0; nj < 2; ++nj) {
                const int r = crow + 16 * mi, cc = ccol + 8 * nj;
                *(float2*)&lg[r * Ek + cc]       = make_float2(acc[mi][nj][0], acc[mi][nj][1]);
                *(float2*)&lg[(r + 8) * Ek + cc] = make_float2(acc[mi][nj][2], acc[mi][nj][3]);
            }
    }
    __syncthreads();

    // add bias, write logits to gmem + smem
    const float* bs = (const float*)(smem + SM_BIAS);
    {
        const int tl = tid >> 2, eh = (tid & 3) * 16;
        float* lr = lg + tl * Ek + eh;
        float4* orow = (float4*)(out + (size_t)(t0 + tl) * Ek + eh);
#pragma unroll
        for (int q = 0; q < 4; ++q) {
            float4 v = *(float4*)(lr + 4 * q);
            v.x += bs[eh + 4 * q + 0];
            v.y += bs[eh + 4 * q + 1];
            v.z += bs[eh + 4 * q + 2];
            v.w += bs[eh + 4 * q + 3];
            orow[q] = v;
            *(float4*)(lr + 4 * q) = v;
        }
    }
    __syncthreads();

    // per-token: top-3 margin test -> finalize or flag
    if (tid < BM) {
        const int t = t0 + tid;
        const float* lr = lg + tid * Ek;
        float m1 = -INFINITY, m2 = -INFINITY, m3 = -INFINITY;
        int i1 = 0, i2 = 0;
#pragma unroll
        for (int e = 0; e < Ek; ++e) {
            float z = lr[e];
            if (z > m1)      { m3 = m2; m2 = m1; i2 = i1; m1 = z; i1 = e; }
            else if (z > m2) { m3 = m2; m2 = z; i2 = e; }
            else if (z > m3) { m3 = z; }
        }
        if ((m1 - m2 < THETA) || (m2 - m3 < THETA)) {
            int slot = atomicAdd(&g_flagcnt, 1);
            g_flags[slot] = t;
        } else {
            float ed = expf(m2 - m1);
            float w1 = 1.0f / (1.0f + ed);
            float w2 = ed * w1;
            out[offW + (size_t)t * TOPK + 0] = w1;
            out[offW + (size_t)t * TOPK + 1] = w2;
            out[offI + (size_t)t * TOPK + 0] = (float)i1;
            out[offI + (size_t)t * TOPK + 1] = (float)i2;
            out[offM + ((size_t)i1 * TOPK + 0) * (size_t)T + t] = 1.0f;
            out[offM + ((size_t)i2 * TOPK + 1) * (size_t)T + t] = 1.0f;
        }
    }
}

// ---------------- pass 2: candidate-only exact refinement, warp per token ----------------
__device__ __forceinline__ float warp_dot4k(const float4* __restrict__ xr,
                                            const float4* __restrict__ wr, int lid) {
    float a = 0.f;
#pragma unroll 8
    for (int i = lid; i < Dk / 4; i += 32) {
        float4 xv = xr[i], wv = wr[i];
        a = fmaf(xv.x, wv.x, a); a = fmaf(xv.y, wv.y, a);
        a = fmaf(xv.z, wv.z, a); a = fmaf(xv.w, wv.w, a);
    }
#pragma unroll
    for (int o = 16; o > 0; o >>= 1) a += __shfl_xor_sync(0xFFFFFFFFu, a, o);
    return a;
}

__global__ __launch_bounds__(256)
void refine_kernel(const float* __restrict__ x,
                   const float* __restrict__ gw,
                   const float* __restrict__ gb,
                   float* __restrict__ out, int T)
{
    const int lid = threadIdx.x & 31;
    const int gwarp = (blockIdx.x * blockDim.x + threadIdx.x) >> 5;
    const int nwarps = (gridDim.x * blockDim.x) >> 5;
    const int nflag = g_flagcnt;

    const size_t offW = (size_t)T * Ek;
    const size_t offI = offW + (size_t)T * TOPK;
    const size_t offM = offI + (size_t)T * TOPK;

    for (int fi = gwarp; fi < nflag; fi += nwarps) {
        const int t = g_flags[fi];
        const float* lrow = out + (size_t)t * Ek;
        float l0 = lrow[lid];         // experts lid, lid+32
        float l1 = lrow[lid + 32];

        // approx top-2 values across warp -> candidate window
        float a1 = fmaxf(l0, l1), a2 = fminf(l0, l1);
#pragma unroll
        for (int o = 16; o > 0; o >>= 1) {
            float b1v = __shfl_xor_sync(0xFFFFFFFFu, a1, o);
            float b2v = __shfl_xor_sync(0xFFFFFFFFu, a2, o);
            float n1 = fmaxf(a1, b1v);
            float n2 = fmaxf(fminf(a1, b1v), fmaxf(a2, b2v));
            a1 = n1; a2 = n2;
        }
        const float thr = a2 - CAND_WIN;

        // exact recompute of candidates
        const float4* xr = (const float4*)(x + (size_t)t * Dk);
        uint32_t mask0 = __ballot_sync(0xFFFFFFFFu, l0 >= thr);
        uint32_t mask1 = __ballot_sync(0xFFFFFFFFu, l1 >= thr);
        while (mask0) {
            int e = __ffs(mask0) - 1; mask0 &= mask0 - 1;
            float ex = warp_dot4k(xr, (const float4*)(gw + (size_t)e * Dk), lid) + __ldg(gb + e);
            if (lid == e) l0 = ex;
        }
        while (mask1) {
            int b = __ffs(mask1) - 1; mask1 &= mask1 - 1;
            int e = b + 32;
            float ex = warp_dot4k(xr, (const float4*)(gw + (size_t)e * Dk), lid) + __ldg(gb + e);
            if (lid == b) l1 = ex;
        }

        // exact top-2 with indices (lower index wins ties)
        float v1, v2; int j1, j2;
        if (l0 >= l1) { v1 = l0; j1 = lid; v2 = l1; j2 = lid + 32; }
        else          { v1 = l1; j1 = lid + 32; v2 = l0; j2 = lid; }
#pragma unroll
        for (int o = 16; o > 0; o >>= 1) {
            float u1 = __shfl_xor_sync(0xFFFFFFFFu, v1, o);
            float u2 = __shfl_xor_sync(0xFFFFFFFFu, v2, o);
            int   k1 = __shfl_xor_sync(0xFFFFFFFFu, j1, o);
            int   k2 = __shfl_xor_sync(0xFFFFFFFFu, j2, o);
            if (u1 > v1 || (u1 == v1 && k1 < j1)) { v2 = v1; j2 = j1; v1 = u1; j1 = k1; }
            else if (u1 > v2 || (u1 == v2 && k1 < j2)) { v2 = u1; j2 = k1; }
            if (u2 > v1 || (u2 == v1 && k2 < j1)) { v2 = v1; j2 = j1; v1 = u2; j1 = k2; }
            else if (u2 > v2 || (u2 == v2 && k2 < j2)) { v2 = u2; j2 = k2; }
        }

        // write corrected logits for candidate entries
        uint32_t cm0 = __ballot_sync(0xFFFFFFFFu, l0 >= thr);
        uint32_t cm1 = __ballot_sync(0xFFFFFFFFu, l1 >= thr);
        if (cm0 & (1u << lid)) out[(size_t)t * Ek + lid] = l0;
        if (cm1 & (1u << lid)) out[(size_t)t * Ek + lid + 32] = l1;

        if (lid == 0) {
            float ed = expf(v2 - v1);
            float w1 = 1.0f / (1.0f + ed);
            float w2 = ed * w1;
            out[offW + (size_t)t * TOPK + 0] = w1;
            out[offW + (size_t)t * TOPK + 1] = w2;
            out[offI + (size_t)t * TOPK + 0] = (float)j1;
            out[offI + (size_t)t * TOPK + 1] = (float)j2;
            out[offM + ((size_t)j1 * TOPK + 0) * (size_t)T + t] = 1.0f;
            out[offM + ((size_t)j2 * TOPK + 1) * (size_t)T + t] = 1.0f;
        }
    }
}

extern "C" void kernel_launch(void* const* d_in, const int* in_sizes, int n_in,
                              void* d_out, int out_size)
{
    const float* x  = (const float*)d_in[0];
    const float* gw = (const float*)d_in[1];
    const float* gb = (const float*)d_in[2];
    float* out = (float*)d_out;
    const int T = in_sizes[0] / Dk;

    cudaFuncSetAttribute(moe_router_mma, cudaFuncAttributeMaxDynamicSharedMemorySize, SMEM_TOTAL);

    w_prep_kernel<<<256, 256>>>((const float4*)gw);
    moe_router_mma<<<T / BM, NTHR, SMEM_TOTAL>>>(x, gb, out, T);
    refine_kernel<<<148, 256>>>(x, gw, gb, out, T);
}

// round 15
// speedup vs baseline: 1.1413x; 1.1413x over previous
#include <cuda_runtime.h>
#include <cuda_fp16.h>
#include <math.h>
#include <stdint.h>

// MoE Router: warp-specialized fp16 mma.sync GEMM (8 producer + 8 consumer warps,
// 8-deep mbarrier stage ring, no block barriers in main loop)
// + candidate-only exact fp32 refinement of marginal tokens.
// T=16384, D=4096, E=64, top-2.
// Output (float32): logits [T,E] | weights [T,2] | indices [T,2] | mask [E,2,T]

#define Dk 4096
#define Ek 64
#define TOPK 2
#define BM 128
#define KC 64
#define NCHUNK (Dk / KC)
#define NTHR 512
#define NSTAGE 8
#define THETA    2.5e-3f
#define CAND_WIN 5.0e-3f

__device__ __half g_w1[Ek * Dk];    // fp16 gate weights, [E][Dk] k-major
__device__ int    g_flagcnt;
__device__ int    g_flags[16384];

// ---------------- smem layout ----------------
// [128..256) mbarriers (full[8], empty[8]), [512..768) bias, [1024..) 8 stages of (X 16KB | W 8KB)
#define MB_FULL(s)  (128 + (s) * 8)
#define MB_EMPTY(s) (192 + (s) * 8)
#define SM_BIAS 512
#define STG(s)  (1024 + (s) * 24576)
#define XS(s)   STG(s)
#define WS(s)   (STG(s) + 16384)
#define SM_LG   1024
#define SMEM_TOTAL (1024 + NSTAGE * 24576)

// ---------------- helpers ----------------
__device__ __forceinline__ uint32_t smem_u32(const void* p) {
    uint32_t a;
    asm("{ .reg .u64 t; cvta.to.shared.u64 t, %1; cvt.u32.u64 %0, t; }" : "=r"(a) : "l"(p));
    return a;
}
__device__ __forceinline__ uint32_t pack2h(float hi, float lo) {
    uint32_t r;
    asm("cvt.rn.f16x2.f32 %0, %1, %2;" : "=r"(r) : "f"(hi), "f"(lo));
    return r;
}
__device__ __forceinline__ uint2 cvt4h(float4 v) {
    return make_uint2(pack2h(v.y, v.x), pack2h(v.w, v.z));
}
__device__ __forceinline__ void ldm_x4(uint32_t* r, uint32_t addr) {
    asm volatile("ldmatrix.sync.aligned.m8n8.x4.shared.b16 {%0,%1,%2,%3}, [%4];"
        : "=r"(r[0]), "=r"(r[1]), "=r"(r[2]), "=r"(r[3]) : "r"(addr));
}
__device__ __forceinline__ void mma_f16(float* c, const uint32_t* a, uint32_t b0, uint32_t b1) {
    asm volatile("mma.sync.aligned.m16n8k16.row.col.f32.f16.f16.f32 "
        "{%0,%1,%2,%3}, {%4,%5,%6,%7}, {%8,%9}, {%0,%1,%2,%3};"
        : "+f"(c[0]), "+f"(c[1]), "+f"(c[2]), "+f"(c[3])
        : "r"(a[0]), "r"(a[1]), "r"(a[2]), "r"(a[3]), "r"(b0), "r"(b1));
}
#define MBAR_INIT(a, n) asm volatile("mbarrier.init.shared.b64 [%0], %1;" :: "r"(a), "r"(n) : "memory")
#define MBAR_ARRIVE(a)  asm volatile("mbarrier.arrive.shared.b64 _, [%0];" :: "r"(a) : "memory")
#define BAR_CONSUMERS() asm volatile("bar.sync 1, 256;" ::: "memory")

__device__ __forceinline__ void mbar_wait(uint32_t mbar, uint32_t parity) {
    uint32_t done;
    asm volatile(
        "{ .reg .pred p; mbarrier.try_wait.parity.acquire.cta.shared::cta.b64 p, [%1], %2;"
        " selp.b32 %0, 1, 0, p; }" : "=r"(done) : "r"(mbar), "r"(parity) : "memory");
    if (!done) {
        asm volatile(
            "{ .reg .pred P1;\n"
            "WL_%=: mbarrier.try_wait.parity.acquire.cta.shared::cta.b64 P1, [%0], %1, 0x989680;\n"
            "@P1 bra.uni WD_%=;\n"
            "bra.uni WL_%=;\n"
            "WD_%=: }" :: "r"(mbar), "r"(parity) : "memory");
    }
}

// ---------------- aux: convert w to fp16 + reset flag counter ----------------
__global__ void w_prep_kernel(const float4* __restrict__ gw4) {
    int i = blockIdx.x * blockDim.x + threadIdx.x;
    if (i == 0) g_flagcnt = 0;
    ((uint2*)g_w1)[i] = cvt4h(gw4[i]);
}

// ---------------- pass 1 ----------------
__global__ __launch_bounds__(NTHR, 1)
void moe_router_mma(const float* __restrict__ x,
                    const float* __restrict__ gb,
                    float* __restrict__ out, int T)
{
    extern __shared__ char smem[];
    const uint32_t sb = smem_u32(smem);
    const int tid = threadIdx.x;
    const int lid = tid & 31;
    const int wid = tid >> 5;
    const int t0 = blockIdx.x * BM;

    const size_t offW = (size_t)T * Ek;
    const size_t offI = offW + (size_t)T * TOPK;
    const size_t offM = offI + (size_t)T * TOPK;

    if (tid < 16) ((float4*)(smem + SM_BIAS))[tid] = ((const float4*)gb)[tid];

    // zero this CTA's slice of expert_mask: 128 (e,k) rows, cols [t0, t0+128)
    {
        float4 z4 = make_float4(0.f, 0.f, 0.f, 0.f);
        float* mbase = out + offM + t0;
#pragma unroll
        for (int i = tid; i < 128 * 32; i += NTHR) {
            int row = i >> 5, col = i & 31;
            ((float4*)(mbase + (size_t)row * T))[col] = z4;
        }
    }

    if (tid == 0) {
#pragma unroll
        for (int s = 0; s < NSTAGE; ++s) {
            MBAR_INIT(sb + MB_FULL(s), 4);    // 4 producer warps per stage
            MBAR_INIT(sb + MB_EMPTY(s), 8);   // 8 consumer warps
        }
    }
    __syncthreads();

    if (wid < 8) {
        // ================= CONSUMERS: 8 warps = 4 m-groups x 2 k-split =================
        const int wm = wid & 3;
        const int kw = wid >> 2;
        const int lrow = lid & 15;
        const int lhi = (lid >> 4) << 4;
        const int rsw = (lrow & 7) << 4;
        int arow[2];
#pragma unroll
        for (int mi = 0; mi < 2; ++mi) arow[mi] = (32 * wm + 16 * mi + lrow) * 128;
        int brow[4];
#pragma unroll
        for (int g = 0; g < 4; ++g) brow[g] = (16 * g + lrow) * 128;

        float acc[2][8][4];
#pragma unroll
        for (int mi = 0; mi < 2; ++mi)
#pragma unroll
            for (int nj = 0; nj < 8; ++nj)
#pragma unroll
                for (int q = 0; q < 4; ++q) acc[mi][nj][q] = 0.f;

        for (int c = 0; c < NCHUNK; ++c) {
            const int s = c & (NSTAGE - 1);
            mbar_wait(sb + MB_FULL(s), (c >> 3) & 1);
            const uint32_t xb = sb + XS(s), wb = sb + WS(s);
#pragma unroll
            for (int ks2 = 0; ks2 < 2; ++ks2) {
                const int ks = 2 * kw + ks2;
                const uint32_t kb = (uint32_t)((ks * 32 + lhi) ^ rsw);
                uint32_t a1[2][4], b1[4][4];
#pragma unroll
                for (int mi = 0; mi < 2; ++mi) ldm_x4(a1[mi], xb + arow[mi] + kb);
#pragma unroll
                for (int g = 0; g < 4; ++g)   ldm_x4(b1[g], wb + brow[g] + kb);
#pragma unroll
                for (int mi = 0; mi < 2; ++mi)
#pragma unroll
                    for (int nj = 0; nj < 8; ++nj) {
                        const int g = nj >> 1, hf = nj & 1;
                        mma_f16(acc[mi][nj], a1[mi], b1[g][hf], b1[g][hf + 2]);
                    }
            }
            if (lid == 0) MBAR_ARRIVE(sb + MB_EMPTY(s));
        }

        // ---- epilogue (consumers only; stages 0-1 area reused as lg) ----
        float* lg = (float*)(smem + SM_LG);
        const int crow = 32 * wm + (lid >> 2);
        const int ccol = (lid & 3) * 2;
        BAR_CONSUMERS();   // all consumers past the ring before overwriting stages 0-1
        if (kw == 0) {
#pragma unroll
            for (int mi = 0; mi < 2; ++mi)
#pragma unroll
                for (int nj = 0; nj < 8; ++nj) {
                    const int r = crow + 16 * mi, cc = ccol + 8 * nj;
                    *(float2*)&lg[r * Ek + cc]       = make_float2(acc[mi][nj][0], acc[mi][nj][1]);
                    *(float2*)&lg[(r + 8) * Ek + cc] = make_float2(acc[mi][nj][2], acc[mi][nj][3]);
                }
        }
        BAR_CONSUMERS();
        if (kw == 1) {
#pragma unroll
            for (int mi = 0; mi < 2; ++mi)
#pragma unroll
                for (int nj = 0; nj < 8; ++nj) {
                    const int r = crow + 16 * mi, cc = ccol + 8 * nj;
                    float2* p0 = (float2*)&lg[r * Ek + cc];
                    float2* p1 = (float2*)&lg[(r + 8) * Ek + cc];
                    float2 v0 = *p0, v1 = *p1;
                    v0.x += acc[mi][nj][0]; v0.y += acc[mi][nj][1];
                    v1.x += acc[mi][nj][2]; v1.y += acc[mi][nj][3];
                    *p0 = v0; *p1 = v1;
                }
        }
        BAR_CONSUMERS();

        // bias + logits write (256 consumer threads; 8 float4 per thread)
        const float* bs = (const float*)(smem + SM_BIAS);
        {
            const int tl = tid >> 1, eh = (tid & 1) * 32;
            float* lr = lg + tl * Ek + eh;
            float4* orow = (float4*)(out + (size_t)(t0 + tl) * Ek + eh);
#pragma unroll
            for (int q = 0; q < 8; ++q) {
                float4 v = *(float4*)(lr + 4 * q);
                v.x += bs[eh + 4 * q + 0];
                v.y += bs[eh + 4 * q + 1];
                v.z += bs[eh + 4 * q + 2];
                v.w += bs[eh + 4 * q + 3];
                orow[q] = v;
                *(float4*)(lr + 4 * q) = v;
            }
        }
        BAR_CONSUMERS();

        // per-token: top-3 margin test -> finalize or flag
        if (tid < BM) {
            const int t = t0 + tid;
            const float* lr = lg + tid * Ek;
            float m1 = -INFINITY, m2 = -INFINITY, m3 = -INFINITY;
            int i1 = 0, i2 = 0;
#pragma unroll
            for (int e = 0; e < Ek; ++e) {
                float z = lr[e];
                if (z > m1)      { m3 = m2; m2 = m1; i2 = i1; m1 = z; i1 = e; }
                else if (z > m2) { m3 = m2; m2 = z; i2 = e; }
                else if (z > m3) { m3 = z; }
            }
            if ((m1 - m2 < THETA) || (m2 - m3 < THETA)) {
                int slot = atomicAdd(&g_flagcnt, 1);
                g_flags[slot] = t;
            } else {
                float ed = expf(m2 - m1);
                float w1 = 1.0f / (1.0f + ed);
                float w2 = ed * w1;
                out[offW + (size_t)t * TOPK + 0] = w1;
                out[offW + (size_t)t * TOPK + 1] = w2;
                out[offI + (size_t)t * TOPK + 0] = (float)i1;
                out[offI + (size_t)t * TOPK + 1] = (float)i2;
                out[offM + ((size_t)i1 * TOPK + 0) * (size_t)T + t] = 1.0f;
                out[offM + ((size_t)i2 * TOPK + 1) * (size_t)T + t] = 1.0f;
            }
        }
    } else {
        // ================= PRODUCERS: 8 warps; set 0 -> even chunks, set 1 -> odd =================
        const int pw = wid - 8;
        const int set = pw >> 2;
        const int base = (pw & 3) * 32 + lid;     // 0..127 within set

        for (int c = set; c < NCHUNK; c += 2) {
            const int s = c & (NSTAGE - 1);
            if (c >= NSTAGE) mbar_wait(sb + MB_EMPTY(s), ((c - NSTAGE) >> 3) & 1);
            const int d = c * KC;

            float4 xv[16];
#pragma unroll
            for (int i = 0; i < 16; ++i) {
                const int idx = base + 128 * i;
                const int row = idx >> 4, seg = idx & 15;
                xv[i] = *(const float4*)(x + (size_t)(t0 + row) * Dk + d + 4 * seg);
            }
            uint4 wv[4];
#pragma unroll
            for (int i = 0; i < 4; ++i) {
                const int idx = base + 128 * i;
                const int r = idx >> 3, sg = idx & 7;
                wv[i] = *(const uint4*)((const char*)g_w1 + ((size_t)r * Dk + d + sg * 8) * 2);
            }
#pragma unroll
            for (int i = 0; i < 16; ++i) {
                const int idx = base + 128 * i;
                const int row = idx >> 4, seg = idx & 15;
                *(uint2*)(smem + XS(s) + row * 128 + ((seg * 8) ^ ((row & 7) << 4))) = cvt4h(xv[i]);
            }
#pragma unroll
            for (int i = 0; i < 4; ++i) {
                const int idx = base + 128 * i;
                const int r = idx >> 3, sg = idx & 7;
                *(uint4*)(smem + WS(s) + r * 128 + ((sg * 16) ^ ((r & 7) << 4))) = wv[i];
            }
            if (lid == 0) MBAR_ARRIVE(sb + MB_FULL(s));
        }
    }
}

// ---------------- pass 2: candidate-only exact refinement, warp per token ----------------
__device__ __forceinline__ float warp_dot4k(const float4* __restrict__ xr,
                                            const float4* __restrict__ wr, int lid) {
    float a = 0.f;
#pragma unroll 8
    for (int i = lid; i < Dk / 4; i += 32) {
        float4 xv = xr[i], wv = wr[i];
        a = fmaf(xv.x, wv.x, a); a = fmaf(xv.y, wv.y, a);
        a = fmaf(xv.z, wv.z, a); a = fmaf(xv.w, wv.w, a);
    }
#pragma unroll
    for (int o = 16; o > 0; o >>= 1) a += __shfl_xor_sync(0xFFFFFFFFu, a, o);
    return a;
}

__global__ __launch_bounds__(256)
void refine_kernel(const float* __restrict__ x,
                   const float* __restrict__ gw,
                   const float* __restrict__ gb,
                   float* __restrict__ out, int T)
{
    const int lid = threadIdx.x & 31;
    const int gwarp = (blockIdx.x * blockDim.x + threadIdx.x) >> 5;
    const int nwarps = (gridDim.x * blockDim.x) >> 5;
    const int nflag = g_flagcnt;

    const size_t offW = (size_t)T * Ek;
    const size_t offI = offW + (size_t)T * TOPK;
    const size_t offM = offI + (size_t)T * TOPK;

    for (int fi = gwarp; fi < nflag; fi += nwarps) {
        const int t = g_flags[fi];
        const float* lrow = out + (size_t)t * Ek;
        float l0 = lrow[lid];
        float l1 = lrow[lid + 32];

        float a1 = fmaxf(l0, l1), a2 = fminf(l0, l1);
#pragma unroll
        for (int o = 16; o > 0; o >>= 1) {
            float b1v = __shfl_xor_sync(0xFFFFFFFFu, a1, o);
            float b2v = __shfl_xor_sync(0xFFFFFFFFu, a2, o);
            float n1 = fmaxf(a1, b1v);
            float n2 = fmaxf(fminf(a1, b1v), fmaxf(a2, b2v));
            a1 = n1; a2 = n2;
        }
        const float thr = a2 - CAND_WIN;

        const float4* xr = (const float4*)(x + (size_t)t * Dk);
        uint32_t mask0 = __ballot_sync(0xFFFFFFFFu, l0 >= thr);
        uint32_t mask1 = __ballot_sync(0xFFFFFFFFu, l1 >= thr);
        while (mask0) {
            int e = __ffs(mask0) - 1; mask0 &= mask0 - 1;
            float ex = warp_dot4k(xr, (const float4*)(gw + (size_t)e * Dk), lid) + __ldg(gb + e);
            if (lid == e) l0 = ex;
        }
        while (mask1) {
            int b = __ffs(mask1) - 1; mask1 &= mask1 - 1;
            int e = b + 32;
            float ex = warp_dot4k(xr, (const float4*)(gw + (size_t)e * Dk), lid) + __ldg(gb + e);
            if (lid == b) l1 = ex;
        }

        float v1, v2; int j1, j2;
        if (l0 >= l1) { v1 = l0; j1 = lid; v2 = l1; j2 = lid + 32; }
        else          { v1 = l1; j1 = lid + 32; v2 = l0; j2 = lid; }
#pragma unroll
        for (int o = 16; o > 0; o >>= 1) {
            float u1 = __shfl_xor_sync(0xFFFFFFFFu, v1, o);
            float u2 = __shfl_xor_sync(0xFFFFFFFFu, v2, o);
            int   k1 = __shfl_xor_sync(0xFFFFFFFFu, j1, o);
            int   k2 = __shfl_xor_sync(0xFFFFFFFFu, j2, o);
            if (u1 > v1 || (u1 == v1 && k1 < j1)) { v2 = v1; j2 = j1; v1 = u1; j1 = k1; }
            else if (u1 > v2 || (u1 == v2 && k1 < j2)) { v2 = u1; j2 = k1; }
            if (u2 > v1 || (u2 == v1 && k2 < j1)) { v2 = v1; j2 = j1; v1 = u2; j1 = k2; }
            else if (u2 > v2 || (u2 == v2 && k2 < j2)) { v2 = u2; j2 = k2; }
        }

        uint32_t cm0 = __ballot_sync(0xFFFFFFFFu, l0 >= thr);
        uint32_t cm1 = __ballot_sync(0xFFFFFFFFu, l1 >= thr);
        if (cm0 & (1u << lid)) out[(size_t)t * Ek + lid] = l0;
        if (cm1 & (1u << lid)) out[(size_t)t * Ek + lid + 32] = l1;

        if (lid == 0) {
            float ed = expf(v2 - v1);
            float w1 = 1.0f / (1.0f + ed);
            float w2 = ed * w1;
            out[offW + (size_t)t * TOPK + 0] = w1;
            out[offW + (size_t)t * TOPK + 1] = w2;
            out[offI + (size_t)t * TOPK + 0] = (float)j1;
            out[offI + (size_t)t * TOPK + 1] = (float)j2;
            out[offM + ((size_t)j1 * TOPK + 0) * (size_t)T + t] = 1.0f;
            out[offM + ((size_t)j2 * TOPK + 1) * (size_t)T + t] = 1.0f;
        }
    }
}

extern "C" void kernel_launch(void* const* d_in, const int* in_sizes, int n_in,
                              void* d_out, int out_size)
{
    const float* x  = (const float*)d_in[0];
    const float* gw = (const float*)d_in[1];
    const float* gb = (const float*)d_in[2];
    float* out = (float*)d_out;
    const int T = in_sizes[0] / Dk;

    cudaFuncSetAttribute(moe_router_mma, cudaFuncAttributeMaxDynamicSharedMemorySize, SMEM_TOTAL);

    w_prep_kernel<<<256, 256>>>((const float4*)gw);
    moe_router_mma<<<T / BM, NTHR, SMEM_TOTAL>>>(x, gb, out, T);
    refine_kernel<<<148, 256>>>(x, gw, gb, out, T);
}